// round 4
// baseline (speedup 1.0000x reference)
#include <cuda_runtime.h>
#include <math.h>
#include <stdint.h>

#define S_TOT 7681
#define C_DIM 256

// ---------------- scratch (static device globals; no allocation) ----------
__device__ float g_q   [S_TOT * C_DIM];
__device__ float g_val [S_TOT * C_DIM];
__device__ float g_off [S_TOT * C_DIM];
__device__ float g_attn[S_TOT * 128];
__device__ float g_samp[S_TOT * C_DIM];
__device__ float g_tmp [S_TOT * C_DIM];
__device__ float g_ffh [S_TOT * 1024];

__constant__ int c_H [4] = {76, 38, 19, 10};
__constant__ int c_W [4] = {76, 38, 19, 10};
__constant__ int c_ST[4] = {0, 5776, 7220, 7581};

// ---------------- elementwise -------------------------------------------
__global__ __launch_bounds__(256) void copy_kernel(float* __restrict__ dst,
                                                   const float* __restrict__ src) {
    int i = blockIdx.x * 256 + threadIdx.x;
    dst[i] = src[i];
}

__global__ __launch_bounds__(256) void add_kernel(float* __restrict__ dst,
                                                  const float* __restrict__ a,
                                                  const float* __restrict__ b) {
    int i = blockIdx.x * 256 + threadIdx.x;
    dst[i] = a[i] + b[i];
}

// ---------------- tf32 tensor-core GEMM ----------------------------------
__device__ __forceinline__ void cp16(uint32_t s, const void* g) {
    asm volatile("cp.async.cg.shared.global [%0], [%1], 16;" :: "r"(s), "l"(g) : "memory");
}

__device__ __forceinline__ void mma8(float c[4], const uint32_t a[4], const uint32_t b[2]) {
    asm volatile(
        "mma.sync.aligned.m16n8k8.row.col.f32.tf32.tf32.f32 "
        "{%0,%1,%2,%3}, {%4,%5,%6,%7}, {%8,%9}, {%0,%1,%2,%3};"
        : "+f"(c[0]), "+f"(c[1]), "+f"(c[2]), "+f"(c[3])
        : "r"(a[0]), "r"(a[1]), "r"(a[2]), "r"(a[3]), "r"(b[0]), "r"(b[1]));
}

// C[M,N] = A[M,K] @ B[K,N] + bias (+relu). BM=128, BK=16, 256 threads.
// 8 warps as 4 (M) x 2 (N); warp tile 32 x (BN/2); m16n8k8 tf32 mma.
// fp32 inputs fed to the tf32 MMA as raw bits (HW truncates the mantissa).
template<int BN, int RELU>
__global__ __launch_bounds__(256, 2) void gemm_tf32_kernel(
    const float* __restrict__ A, const float* __restrict__ B,
    const float* __restrict__ bias, float* __restrict__ C,
    int M, int N, int K)
{
    constexpr int BM = 128, BK = 16;
    constexpr int NT = BN / 16;           // n8 tiles per warp
    constexpr int BROW = BN / 4;          // float4 per B row

    __shared__ float As[2][BM][20];       // pad to 20 floats (80B, 16B aligned)
    __shared__ float Bs[2][BK][BN + 4];   // pad +4 floats (16B aligned row stride)

    const int tid  = threadIdx.x;
    const int lane = tid & 31;
    const int wid  = tid >> 5;
    const int wm   = wid & 3;             // warp row 0..3
    const int wn   = wid >> 2;            // warp col 0..1
    const int m0   = blockIdx.y * BM;
    const int n0   = blockIdx.x * BN;

    float acc[2][NT][4];
    #pragma unroll
    for (int mt = 0; mt < 2; mt++)
        #pragma unroll
        for (int nt = 0; nt < NT; nt++)
            #pragma unroll
            for (int j = 0; j < 4; j++) acc[mt][nt][j] = 0.f;

    auto prefetch = [&](int buf, int k0) {
        #pragma unroll
        for (int i = 0; i < 2; i++) {              // A: 128x16 = 512 float4
            int f = tid + i * 256;
            int r = f >> 2, c = (f & 3) * 4;
            int gm = m0 + r; if (gm > M - 1) gm = M - 1;   // clamp; extra rows unused
            cp16((uint32_t)__cvta_generic_to_shared(&As[buf][r][c]),
                 A + (size_t)gm * K + k0 + c);
        }
        #pragma unroll
        for (int i = 0; i < BN / 64; i++) {        // B: 16xBN
            int f = tid + i * 256;
            int r = f / BROW, c = (f % BROW) * 4;
            cp16((uint32_t)__cvta_generic_to_shared(&Bs[buf][r][c]),
                 B + (size_t)(k0 + r) * N + n0 + c);
        }
        asm volatile("cp.async.commit_group;" ::: "memory");
    };

    prefetch(0, 0);
    int buf = 0;
    for (int k0 = 0; k0 < K; k0 += BK) {
        const bool has_next = (k0 + BK) < K;
        if (has_next) {
            prefetch(buf ^ 1, k0 + BK);
            asm volatile("cp.async.wait_group 1;" ::: "memory");
        } else {
            asm volatile("cp.async.wait_group 0;" ::: "memory");
        }
        __syncthreads();

        #pragma unroll
        for (int kc = 0; kc < BK; kc += 8) {
            const int mb = wm * 32 + (lane >> 2);
            const int kk = kc + (lane & 3);
            uint32_t afr[2][4];
            #pragma unroll
            for (int mt = 0; mt < 2; mt++) {
                afr[mt][0] = __float_as_uint(As[buf][mb + mt * 16    ][kk]);
                afr[mt][1] = __float_as_uint(As[buf][mb + mt * 16 + 8][kk]);
                afr[mt][2] = __float_as_uint(As[buf][mb + mt * 16    ][kk + 4]);
                afr[mt][3] = __float_as_uint(As[buf][mb + mt * 16 + 8][kk + 4]);
            }
            uint32_t bfr[NT][2];
            #pragma unroll
            for (int nt = 0; nt < NT; nt++) {
                const int kr = kc + (lane & 3);
                const int nc = wn * (BN / 2) + nt * 8 + (lane >> 2);
                bfr[nt][0] = __float_as_uint(Bs[buf][kr    ][nc]);
                bfr[nt][1] = __float_as_uint(Bs[buf][kr + 4][nc]);
            }
            #pragma unroll
            for (int mt = 0; mt < 2; mt++)
                #pragma unroll
                for (int nt = 0; nt < NT; nt++)
                    mma8(acc[mt][nt], afr[mt], bfr[nt]);
        }
        __syncthreads();
        buf ^= 1;
    }

    // epilogue: bias (+relu), float2 stores
    #pragma unroll
    for (int mt = 0; mt < 2; mt++) {
        int gm = m0 + wm * 32 + mt * 16 + (lane >> 2);
        #pragma unroll
        for (int nt = 0; nt < NT; nt++) {
            int gn = n0 + wn * (BN / 2) + nt * 8 + 2 * (lane & 3);
            float b0 = bias[gn], b1 = bias[gn + 1];
            float v0 = acc[mt][nt][0] + b0, v1 = acc[mt][nt][1] + b1;
            float v2 = acc[mt][nt][2] + b0, v3 = acc[mt][nt][3] + b1;
            if (RELU) {
                v0 = fmaxf(v0, 0.f); v1 = fmaxf(v1, 0.f);
                v2 = fmaxf(v2, 0.f); v3 = fmaxf(v3, 0.f);
            }
            if (gm < M)
                *reinterpret_cast<float2*>(C + (size_t)gm * N + gn) = make_float2(v0, v1);
            if (gm + 8 < M)
                *reinterpret_cast<float2*>(C + (size_t)(gm + 8) * N + gn) = make_float2(v2, v3);
        }
    }
}

// ---------------- MSDA sampling: one warp per (s, head) -------------------
__global__ __launch_bounds__(256) void msda_kernel(
    const float* __restrict__ val, const float* __restrict__ off,
    const float* __restrict__ attn, const float* __restrict__ vr,
    float* __restrict__ out)
{
    const unsigned FULL = 0xffffffffu;
    int w = blockIdx.x * 8 + (threadIdx.x >> 5);
    int lane = threadIdx.x & 31;
    if (w >= S_TOT * 8) return;
    int s = w >> 3;
    int m = w & 7;

    // softmax over 16 logits (lanes 0..15 hold them)
    float logit = -INFINITY;
    if (lane < 16) logit = attn[(size_t)s * 128 + m * 16 + lane];
    float mx = logit;
    #pragma unroll
    for (int o = 16; o > 0; o >>= 1) mx = fmaxf(mx, __shfl_xor_sync(FULL, mx, o));
    float e = (lane < 16) ? expf(logit - mx) : 0.f;
    float sum = e;
    #pragma unroll
    for (int o = 16; o > 0; o >>= 1) sum += __shfl_xor_sync(FULL, sum, o);
    float wn = e / sum;   // valid in lanes 0..15

    int lvlS = (s >= 7581) ? 3 : (s >= 7220) ? 2 : (s >= 5776) ? 1 : 0;
    int idx = s - c_ST[lvlS];
    int Ws = c_W[lvlS], Hs = c_H[lvlS];
    int row = idx / Ws, col = idx - row * Ws;
    float bx = (col + 0.5f) / (vr[lvlS * 2 + 0] * (float)Ws);
    float by = (row + 0.5f) / (vr[lvlS * 2 + 1] * (float)Hs);

    float offv = off[(size_t)s * 256 + m * 32 + lane];

    float acc = 0.f;
    #pragma unroll
    for (int lvl = 0; lvl < 4; lvl++) {
        int H = c_H[lvl], W = c_W[lvl], st = c_ST[lvl];
        float refx = bx * vr[lvl * 2 + 0];
        float refy = by * vr[lvl * 2 + 1];
        #pragma unroll
        for (int p = 0; p < 4; p++) {
            float ox = __shfl_sync(FULL, offv, lvl * 8 + p * 2 + 0);
            float oy = __shfl_sync(FULL, offv, lvl * 8 + p * 2 + 1);
            float aw = __shfl_sync(FULL, wn, lvl * 4 + p);
            float lx = refx + ox / (float)W;
            float ly = refy + oy / (float)H;
            float x = lx * (float)W - 0.5f;
            float y = ly * (float)H - 0.5f;
            float x0f = floorf(x), y0f = floorf(y);
            int x0 = (int)x0f, y0 = (int)y0f;
            float dx = x - x0f, dy = y - y0f;

            float samp = 0.f;
            const float* vb = val + (size_t)st * 256 + m * 32 + lane;
            if (x0 >= 0 && x0 < W && y0 >= 0 && y0 < H)
                samp += (1.f - dy) * (1.f - dx) * vb[(size_t)(y0 * W + x0) * 256];
            if (x0 + 1 >= 0 && x0 + 1 < W && y0 >= 0 && y0 < H)
                samp += (1.f - dy) * dx * vb[(size_t)(y0 * W + x0 + 1) * 256];
            if (x0 >= 0 && x0 < W && y0 + 1 >= 0 && y0 + 1 < H)
                samp += dy * (1.f - dx) * vb[(size_t)((y0 + 1) * W + x0) * 256];
            if (x0 + 1 >= 0 && x0 + 1 < W && y0 + 1 >= 0 && y0 + 1 < H)
                samp += dy * dx * vb[(size_t)((y0 + 1) * W + x0 + 1) * 256];

            acc += aw * samp;
        }
    }
    out[(size_t)s * 256 + m * 32 + lane] = acc;
}

// ---------------- residual add + LayerNorm (in place on x) ---------------
__device__ __forceinline__ float block_sum(float v) {
    __shared__ float sh[8];
    int lane = threadIdx.x & 31, wid = threadIdx.x >> 5;
    #pragma unroll
    for (int o = 16; o > 0; o >>= 1) v += __shfl_xor_sync(0xffffffffu, v, o);
    if (lane == 0) sh[wid] = v;
    __syncthreads();
    if (wid == 0) {
        float t = (lane < 8) ? sh[lane] : 0.f;
        #pragma unroll
        for (int o = 4; o > 0; o >>= 1) t += __shfl_xor_sync(0xffffffffu, t, o);
        if (lane == 0) sh[0] = t;
    }
    __syncthreads();
    float r = sh[0];
    __syncthreads();
    return r;
}

__global__ __launch_bounds__(256) void add_ln_kernel(
    float* __restrict__ x, const float* __restrict__ r,
    const float* __restrict__ g, const float* __restrict__ b)
{
    int s = blockIdx.x;
    int t = threadIdx.x;
    size_t i = (size_t)s * 256 + t;
    float v = x[i] + r[i];
    float mean = block_sum(v) * (1.f / 256.f);
    float d = v - mean;
    float var = block_sum(d * d) * (1.f / 256.f);
    float inv = rsqrtf(var + 1e-5f);
    x[i] = d * inv * g[t] + b[t];
}

// ---------------- launch --------------------------------------------------
extern "C" void kernel_launch(void* const* d_in, const int* in_sizes, int n_in,
                              void* d_out, int out_size) {
    const float* src    = (const float*)d_in[0];
    const float* pos    = (const float*)d_in[1];
    const float* vr     = (const float*)d_in[2];
    const float* W_off  = (const float*)d_in[6];
    const float* b_off  = (const float*)d_in[7];
    const float* W_attn = (const float*)d_in[8];
    const float* b_attn = (const float*)d_in[9];
    const float* W_val  = (const float*)d_in[10];
    const float* b_val  = (const float*)d_in[11];
    const float* W_out  = (const float*)d_in[12];
    const float* b_out  = (const float*)d_in[13];
    const float* ln1_g  = (const float*)d_in[14];
    const float* ln1_b  = (const float*)d_in[15];
    const float* W_ff1  = (const float*)d_in[16];
    const float* b_ff1  = (const float*)d_in[17];
    const float* W_ff2  = (const float*)d_in[18];
    const float* b_ff2  = (const float*)d_in[19];
    const float* ln2_g  = (const float*)d_in[20];
    const float* ln2_b  = (const float*)d_in[21];

    float* x = (float*)d_out;   // running activation, ends as the output

    float *q, *val, *off, *attn, *samp, *tmp, *ffh;
    cudaGetSymbolAddress((void**)&q,    g_q);
    cudaGetSymbolAddress((void**)&val,  g_val);
    cudaGetSymbolAddress((void**)&off,  g_off);
    cudaGetSymbolAddress((void**)&attn, g_attn);
    cudaGetSymbolAddress((void**)&samp, g_samp);
    cudaGetSymbolAddress((void**)&tmp,  g_tmp);
    cudaGetSymbolAddress((void**)&ffh,  g_ffh);

    const int S = S_TOT;
    const int MB = 61;                      // ceil(7681/128)
    const dim3 g256(4, MB);                 // BN=64  -> 244 blocks
    const dim3 g128a(2, MB);                // BN=64  -> 122 blocks (attn, N=128)
    const dim3 g1024(8, MB);                // BN=128 -> 488 blocks

    copy_kernel<<<S, 256>>>(x, src);

    for (int l = 0; l < 3; l++) {
        add_kernel<<<S, 256>>>(q, x, pos);
        gemm_tf32_kernel<64, 0><<<g256, 256>>>(x, W_val + (size_t)l * 65536,
                                               b_val + l * 256, val, S, 256, 256);
        gemm_tf32_kernel<64, 0><<<g256, 256>>>(q, W_off + (size_t)l * 65536,
                                               b_off + l * 256, off, S, 256, 256);
        gemm_tf32_kernel<64, 0><<<g128a, 256>>>(q, W_attn + (size_t)l * 32768,
                                                b_attn + l * 128, attn, S, 128, 256);
        msda_kernel<<<S, 256>>>(val, off, attn, vr, samp);
        gemm_tf32_kernel<64, 0><<<g256, 256>>>(samp, W_out + (size_t)l * 65536,
                                               b_out + l * 256, tmp, S, 256, 256);
        add_ln_kernel<<<S, 256>>>(x, tmp, ln1_g + l * 256, ln1_b + l * 256);
        gemm_tf32_kernel<128, 1><<<g1024, 256>>>(x, W_ff1 + (size_t)l * 262144,
                                                 b_ff1 + l * 1024, ffh, S, 1024, 256);
        gemm_tf32_kernel<64, 0><<<g256, 256>>>(ffh, W_ff2 + (size_t)l * 262144,
                                               b_ff2 + l * 256, tmp, S, 256, 1024);
        add_ln_kernel<<<S, 256>>>(x, tmp, ln2_g + l * 256, ln2_b + l * 256);
    }
}

// round 6
// speedup vs baseline: 1.5856x; 1.5856x over previous
#include <cuda_runtime.h>
#include <math.h>
#include <stdint.h>

#define S_TOT 7681
#define C_DIM 256

// ---------------- scratch (static device globals; no allocation) ----------
__device__ float g_q   [S_TOT * C_DIM];
__device__ float g_val [S_TOT * C_DIM];
__device__ float g_off [S_TOT * C_DIM];
__device__ float g_attn[S_TOT * 128];
__device__ float g_samp[S_TOT * C_DIM];
__device__ float g_tmp [S_TOT * C_DIM];
__device__ float g_ffh [S_TOT * 1024];

__constant__ int c_H [4] = {76, 38, 19, 10};
__constant__ int c_W [4] = {76, 38, 19, 10};
__constant__ int c_ST[4] = {0, 5776, 7220, 7581};

// ---------------- elementwise -------------------------------------------
__global__ __launch_bounds__(256) void copy_kernel(float* __restrict__ dst,
                                                   const float* __restrict__ src) {
    int i = blockIdx.x * 256 + threadIdx.x;
    dst[i] = src[i];
}

__global__ __launch_bounds__(256) void add_kernel(float* __restrict__ dst,
                                                  const float* __restrict__ a,
                                                  const float* __restrict__ b) {
    int i = blockIdx.x * 256 + threadIdx.x;
    dst[i] = a[i] + b[i];
}

// ---------------- tf32 tensor-core GEMM ----------------------------------
__device__ __forceinline__ void cp16(uint32_t s, const void* g) {
    asm volatile("cp.async.cg.shared.global [%0], [%1], 16;" :: "r"(s), "l"(g) : "memory");
}

__device__ __forceinline__ void mma8(float c[4], const uint32_t a[4], const uint32_t b[2]) {
    asm volatile(
        "mma.sync.aligned.m16n8k8.row.col.f32.tf32.tf32.f32 "
        "{%0,%1,%2,%3}, {%4,%5,%6,%7}, {%8,%9}, {%0,%1,%2,%3};"
        : "+f"(c[0]), "+f"(c[1]), "+f"(c[2]), "+f"(c[3])
        : "r"(a[0]), "r"(a[1]), "r"(a[2]), "r"(a[3]), "r"(b[0]), "r"(b[1]));
}

// C[M,N] = A[M,K] @ B[K,N] + bias (+relu). 256 threads, BK=16, 2-stage cp.async.
// 8 warps: WM x WN where WM = BM/32. Warp tile = 32 x (BN/WN).
// fp32 inputs fed to the tf32 MMA as raw bits (HW truncates the mantissa).
template<int BM, int BN, int RELU>
__global__ __launch_bounds__(256) void gemm_tf32_kernel(
    const float* __restrict__ A, const float* __restrict__ B,
    const float* __restrict__ bias, float* __restrict__ C,
    int M, int N, int K)
{
    constexpr int BK = 16;
    constexpr int WM = BM / 32;           // warps along M (2 or 4)
    constexpr int WN = 8 / WM;            // warps along N
    constexpr int NT = BN / (WN * 8);     // n8 tiles per warp
    constexpr int BROW = BN / 4;          // float4 per B row
    constexpr int A_ITERS = BM * 4 / 256; // float4 loads per thread for A
    constexpr int B_ITERS = BN / 64;      // float4 loads per thread for B

    __shared__ float As[2][BM][20];       // pad to 20 floats (80B, 16B aligned)
    __shared__ float Bs[2][BK][BN + 4];   // pad +4 floats (16B aligned row stride)

    const int tid  = threadIdx.x;
    const int lane = tid & 31;
    const int wid  = tid >> 5;
    const int wm   = wid % WM;            // warp row
    const int wn   = wid / WM;            // warp col
    const int m0   = blockIdx.y * BM;
    const int n0   = blockIdx.x * BN;

    float acc[2][NT][4];
    #pragma unroll
    for (int mt = 0; mt < 2; mt++)
        #pragma unroll
        for (int nt = 0; nt < NT; nt++)
            #pragma unroll
            for (int j = 0; j < 4; j++) acc[mt][nt][j] = 0.f;

    auto prefetch = [&](int buf, int k0) {
        #pragma unroll
        for (int i = 0; i < A_ITERS; i++) {        // A: BMx16
            int f = tid + i * 256;
            int r = f >> 2, c = (f & 3) * 4;
            int gm = m0 + r; if (gm > M - 1) gm = M - 1;   // clamp; extra rows unused
            cp16((uint32_t)__cvta_generic_to_shared(&As[buf][r][c]),
                 A + (size_t)gm * K + k0 + c);
        }
        #pragma unroll
        for (int i = 0; i < B_ITERS; i++) {        // B: 16xBN
            int f = tid + i * 256;
            int r = f / BROW, c = (f % BROW) * 4;
            cp16((uint32_t)__cvta_generic_to_shared(&Bs[buf][r][c]),
                 B + (size_t)(k0 + r) * N + n0 + c);
        }
        asm volatile("cp.async.commit_group;" ::: "memory");
    };

    prefetch(0, 0);
    int buf = 0;
    for (int k0 = 0; k0 < K; k0 += BK) {
        const bool has_next = (k0 + BK) < K;
        if (has_next) {
            prefetch(buf ^ 1, k0 + BK);
            asm volatile("cp.async.wait_group 1;" ::: "memory");
        } else {
            asm volatile("cp.async.wait_group 0;" ::: "memory");
        }
        __syncthreads();

        #pragma unroll
        for (int kc = 0; kc < BK; kc += 8) {
            const int mb = wm * 32 + (lane >> 2);
            const int kk = kc + (lane & 3);
            uint32_t afr[2][4];
            #pragma unroll
            for (int mt = 0; mt < 2; mt++) {
                afr[mt][0] = __float_as_uint(As[buf][mb + mt * 16    ][kk]);
                afr[mt][1] = __float_as_uint(As[buf][mb + mt * 16 + 8][kk]);
                afr[mt][2] = __float_as_uint(As[buf][mb + mt * 16    ][kk + 4]);
                afr[mt][3] = __float_as_uint(As[buf][mb + mt * 16 + 8][kk + 4]);
            }
            uint32_t bfr[NT][2];
            #pragma unroll
            for (int nt = 0; nt < NT; nt++) {
                const int kr = kc + (lane & 3);
                const int nc = wn * (BN / WN) + nt * 8 + (lane >> 2);
                bfr[nt][0] = __float_as_uint(Bs[buf][kr    ][nc]);
                bfr[nt][1] = __float_as_uint(Bs[buf][kr + 4][nc]);
            }
            #pragma unroll
            for (int mt = 0; mt < 2; mt++)
                #pragma unroll
                for (int nt = 0; nt < NT; nt++)
                    mma8(acc[mt][nt], afr[mt], bfr[nt]);
        }
        __syncthreads();
        buf ^= 1;
    }

    // epilogue: bias (+relu), float2 stores
    #pragma unroll
    for (int mt = 0; mt < 2; mt++) {
        int gm = m0 + wm * 32 + mt * 16 + (lane >> 2);
        #pragma unroll
        for (int nt = 0; nt < NT; nt++) {
            int gn = n0 + wn * (BN / WN) + nt * 8 + 2 * (lane & 3);
            float b0 = bias[gn], b1 = bias[gn + 1];
            float v0 = acc[mt][nt][0] + b0, v1 = acc[mt][nt][1] + b1;
            float v2 = acc[mt][nt][2] + b0, v3 = acc[mt][nt][3] + b1;
            if (RELU) {
                v0 = fmaxf(v0, 0.f); v1 = fmaxf(v1, 0.f);
                v2 = fmaxf(v2, 0.f); v3 = fmaxf(v3, 0.f);
            }
            if (gm < M)
                *reinterpret_cast<float2*>(C + (size_t)gm * N + gn) = make_float2(v0, v1);
            if (gm + 8 < M)
                *reinterpret_cast<float2*>(C + (size_t)(gm + 8) * N + gn) = make_float2(v2, v3);
        }
    }
}

// ---------------- MSDA sampling: one warp per (s, head) -------------------
__global__ __launch_bounds__(256) void msda_kernel(
    const float* __restrict__ val, const float* __restrict__ off,
    const float* __restrict__ attn, const float* __restrict__ vr,
    float* __restrict__ out)
{
    const unsigned FULL = 0xffffffffu;
    int w = blockIdx.x * 8 + (threadIdx.x >> 5);
    int lane = threadIdx.x & 31;
    if (w >= S_TOT * 8) return;
    int s = w >> 3;
    int m = w & 7;

    // softmax over 16 logits (lanes 0..15 hold them)
    float logit = -INFINITY;
    if (lane < 16) logit = attn[(size_t)s * 128 + m * 16 + lane];
    float mx = logit;
    #pragma unroll
    for (int o = 16; o > 0; o >>= 1) mx = fmaxf(mx, __shfl_xor_sync(FULL, mx, o));
    float e = (lane < 16) ? expf(logit - mx) : 0.f;
    float sum = e;
    #pragma unroll
    for (int o = 16; o > 0; o >>= 1) sum += __shfl_xor_sync(FULL, sum, o);
    float wn = e / sum;   // valid in lanes 0..15

    int lvlS = (s >= 7581) ? 3 : (s >= 7220) ? 2 : (s >= 5776) ? 1 : 0;
    int idx = s - c_ST[lvlS];
    int Ws = c_W[lvlS], Hs = c_H[lvlS];
    int row = idx / Ws, col = idx - row * Ws;
    float bx = (col + 0.5f) / (vr[lvlS * 2 + 0] * (float)Ws);
    float by = (row + 0.5f) / (vr[lvlS * 2 + 1] * (float)Hs);

    float offv = off[(size_t)s * 256 + m * 32 + lane];

    float acc = 0.f;
    #pragma unroll
    for (int lvl = 0; lvl < 4; lvl++) {
        int H = c_H[lvl], W = c_W[lvl], st = c_ST[lvl];
        float refx = bx * vr[lvl * 2 + 0];
        float refy = by * vr[lvl * 2 + 1];
        #pragma unroll
        for (int p = 0; p < 4; p++) {
            float ox = __shfl_sync(FULL, offv, lvl * 8 + p * 2 + 0);
            float oy = __shfl_sync(FULL, offv, lvl * 8 + p * 2 + 1);
            float aw = __shfl_sync(FULL, wn, lvl * 4 + p);
            float lx = refx + ox / (float)W;
            float ly = refy + oy / (float)H;
            float x = lx * (float)W - 0.5f;
            float y = ly * (float)H - 0.5f;
            float x0f = floorf(x), y0f = floorf(y);
            int x0 = (int)x0f, y0 = (int)y0f;
            float dx = x - x0f, dy = y - y0f;

            float samp = 0.f;
            const float* vb = val + (size_t)st * 256 + m * 32 + lane;
            if (x0 >= 0 && x0 < W && y0 >= 0 && y0 < H)
                samp += (1.f - dy) * (1.f - dx) * vb[(size_t)(y0 * W + x0) * 256];
            if (x0 + 1 >= 0 && x0 + 1 < W && y0 >= 0 && y0 < H)
                samp += (1.f - dy) * dx * vb[(size_t)(y0 * W + x0 + 1) * 256];
            if (x0 >= 0 && x0 < W && y0 + 1 >= 0 && y0 + 1 < H)
                samp += dy * (1.f - dx) * vb[(size_t)((y0 + 1) * W + x0) * 256];
            if (x0 + 1 >= 0 && x0 + 1 < W && y0 + 1 >= 0 && y0 + 1 < H)
                samp += dy * dx * vb[(size_t)((y0 + 1) * W + x0 + 1) * 256];

            acc += aw * samp;
        }
    }
    out[(size_t)s * 256 + m * 32 + lane] = acc;
}

// ---------------- residual add + LayerNorm (in place on x) ---------------
__device__ __forceinline__ float block_sum(float v) {
    __shared__ float sh[8];
    int lane = threadIdx.x & 31, wid = threadIdx.x >> 5;
    #pragma unroll
    for (int o = 16; o > 0; o >>= 1) v += __shfl_xor_sync(0xffffffffu, v, o);
    if (lane == 0) sh[wid] = v;
    __syncthreads();
    if (wid == 0) {
        float t = (lane < 8) ? sh[lane] : 0.f;
        #pragma unroll
        for (int o = 4; o > 0; o >>= 1) t += __shfl_xor_sync(0xffffffffu, t, o);
        if (lane == 0) sh[0] = t;
    }
    __syncthreads();
    float r = sh[0];
    __syncthreads();
    return r;
}

__global__ __launch_bounds__(256) void add_ln_kernel(
    float* __restrict__ x, const float* __restrict__ r,
    const float* __restrict__ g, const float* __restrict__ b)
{
    int s = blockIdx.x;
    int t = threadIdx.x;
    size_t i = (size_t)s * 256 + t;
    float v = x[i] + r[i];
    float mean = block_sum(v) * (1.f / 256.f);
    float d = v - mean;
    float var = block_sum(d * d) * (1.f / 256.f);
    float inv = rsqrtf(var + 1e-5f);
    x[i] = d * inv * g[t] + b[t];
}

// ---------------- launch --------------------------------------------------
extern "C" void kernel_launch(void* const* d_in, const int* in_sizes, int n_in,
                              void* d_out, int out_size) {
    const float* src    = (const float*)d_in[0];
    const float* pos    = (const float*)d_in[1];
    const float* vr     = (const float*)d_in[2];
    const float* W_off  = (const float*)d_in[6];
    const float* b_off  = (const float*)d_in[7];
    const float* W_attn = (const float*)d_in[8];
    const float* b_attn = (const float*)d_in[9];
    const float* W_val  = (const float*)d_in[10];
    const float* b_val  = (const float*)d_in[11];
    const float* W_out  = (const float*)d_in[12];
    const float* b_out  = (const float*)d_in[13];
    const float* ln1_g  = (const float*)d_in[14];
    const float* ln1_b  = (const float*)d_in[15];
    const float* W_ff1  = (const float*)d_in[16];
    const float* b_ff1  = (const float*)d_in[17];
    const float* W_ff2  = (const float*)d_in[18];
    const float* b_ff2  = (const float*)d_in[19];
    const float* ln2_g  = (const float*)d_in[20];
    const float* ln2_b  = (const float*)d_in[21];

    float* x = (float*)d_out;   // running activation, ends as the output

    float *q, *val, *off, *attn, *samp, *tmp, *ffh;
    cudaGetSymbolAddress((void**)&q,    g_q);
    cudaGetSymbolAddress((void**)&val,  g_val);
    cudaGetSymbolAddress((void**)&off,  g_off);
    cudaGetSymbolAddress((void**)&attn, g_attn);
    cudaGetSymbolAddress((void**)&samp, g_samp);
    cudaGetSymbolAddress((void**)&tmp,  g_tmp);
    cudaGetSymbolAddress((void**)&ffh,  g_ffh);

    const int S = S_TOT;
    const int MB64  = 121;                  // ceil(7681/64)
    const int MB128 = 61;                   // ceil(7681/128)
    const dim3 g256(2, MB64);               // BM=64, BN=128 -> 242 blocks
    const dim3 g128a(1, MB64);              // attn N=128    -> 121 blocks
    const dim3 g1024(8, MB128);             // ff1 BM=128,BN=128 -> 488 blocks

    copy_kernel<<<S, 256>>>(x, src);

    for (int l = 0; l < 3; l++) {
        add_kernel<<<S, 256>>>(q, x, pos);
        gemm_tf32_kernel<64, 128, 0><<<g256, 256>>>(x, W_val + (size_t)l * 65536,
                                                    b_val + l * 256, val, S, 256, 256);
        gemm_tf32_kernel<64, 128, 0><<<g256, 256>>>(q, W_off + (size_t)l * 65536,
                                                    b_off + l * 256, off, S, 256, 256);
        gemm_tf32_kernel<64, 128, 0><<<g128a, 256>>>(q, W_attn + (size_t)l * 32768,
                                                     b_attn + l * 128, attn, S, 128, 256);
        msda_kernel<<<S, 256>>>(val, off, attn, vr, samp);
        gemm_tf32_kernel<64, 128, 0><<<g256, 256>>>(samp, W_out + (size_t)l * 65536,
                                                    b_out + l * 256, tmp, S, 256, 256);
        add_ln_kernel<<<S, 256>>>(x, tmp, ln1_g + l * 256, ln1_b + l * 256);
        gemm_tf32_kernel<128, 128, 1><<<g1024, 256>>>(x, W_ff1 + (size_t)l * 262144,
                                                      b_ff1 + l * 1024, ffh, S, 1024, 256);
        gemm_tf32_kernel<64, 128, 0><<<g256, 256>>>(ffh, W_ff2 + (size_t)l * 262144,
                                                    b_ff2 + l * 256, tmp, S, 256, 1024);
        add_ln_kernel<<<S, 256>>>(x, tmp, ln2_g + l * 256, ln2_b + l * 256);
    }
}

// round 7
// speedup vs baseline: 1.6694x; 1.0529x over previous
#include <cuda_runtime.h>
#include <math.h>
#include <stdint.h>

#define S_TOT 7681
#define C_DIM 256

// ---------------- scratch (static device globals; no allocation) ----------
__device__ float g_q   [S_TOT * C_DIM];
__device__ float g_val [S_TOT * C_DIM];
__device__ float g_off [S_TOT * C_DIM];
__device__ float g_attn[S_TOT * 128];
__device__ float g_samp[S_TOT * C_DIM];
__device__ float g_tmp [S_TOT * C_DIM];
__device__ float g_tmp2[S_TOT * C_DIM];
__device__ float g_ffh [S_TOT * 1024];

__constant__ int c_H [4] = {76, 38, 19, 10};
__constant__ int c_W [4] = {76, 38, 19, 10};
__constant__ int c_ST[4] = {0, 5776, 7220, 7581};

// ---------------- elementwise -------------------------------------------
__global__ __launch_bounds__(256) void copy_kernel(float* __restrict__ dst,
                                                   const float* __restrict__ src) {
    int i = blockIdx.x * 256 + threadIdx.x;
    dst[i] = src[i];
}

__global__ __launch_bounds__(256) void add_kernel(float* __restrict__ dst,
                                                  const float* __restrict__ a,
                                                  const float* __restrict__ b) {
    int i = blockIdx.x * 256 + threadIdx.x;
    dst[i] = a[i] + b[i];
}

// ---------------- tf32 tensor-core GEMM primitives ------------------------
__device__ __forceinline__ void cp16(uint32_t s, const void* g) {
    asm volatile("cp.async.cg.shared.global [%0], [%1], 16;" :: "r"(s), "l"(g) : "memory");
}

__device__ __forceinline__ void mma8(float c[4], const uint32_t a[4], const uint32_t b[2]) {
    asm volatile(
        "mma.sync.aligned.m16n8k8.row.col.f32.tf32.tf32.f32 "
        "{%0,%1,%2,%3}, {%4,%5,%6,%7}, {%8,%9}, {%0,%1,%2,%3};"
        : "+f"(c[0]), "+f"(c[1]), "+f"(c[2]), "+f"(c[3])
        : "r"(a[0]), "r"(a[1]), "r"(a[2]), "r"(a[3]), "r"(b[0]), "r"(b[1]));
}

// Core mainloop + epilogue, shared by all GEMM kernels.
// BM x BN block tile, BK=16, 256 threads (8 warps: WM x WN), warp tile 32 x (BN/WN).
// A is [M, lda] (row-major, lda = full K of the matrix); loop runs K elements.
// fp32 fed to tf32 MMA as raw bits (HW truncates mantissa).
template<int BM, int BN, int RELU>
__device__ __forceinline__ void gemm_body(
    const float* __restrict__ A, const float* __restrict__ B,
    const float* __restrict__ bias, float* __restrict__ C,
    int M, int N, int K, int lda, int m0, int n0, int use_bias,
    float (*As)[BM][20], float (*Bs)[16][BN + 4])
{
    constexpr int BK = 16;
    constexpr int WM = BM / 32;
    constexpr int WN = 8 / WM;
    constexpr int NT = BN / (WN * 8);
    constexpr int BROW = BN / 4;
    constexpr int A_ITERS = BM * 4 / 256;
    constexpr int B_ITERS = BN / 64;

    const int tid  = threadIdx.x;
    const int lane = tid & 31;
    const int wid  = tid >> 5;
    const int wm   = wid % WM;
    const int wn   = wid / WM;

    float acc[2][NT][4];
    #pragma unroll
    for (int mt = 0; mt < 2; mt++)
        #pragma unroll
        for (int nt = 0; nt < NT; nt++)
            #pragma unroll
            for (int j = 0; j < 4; j++) acc[mt][nt][j] = 0.f;

    auto prefetch = [&](int buf, int k0) {
        #pragma unroll
        for (int i = 0; i < A_ITERS; i++) {
            int f = tid + i * 256;
            int r = f >> 2, c = (f & 3) * 4;
            int gm = m0 + r; if (gm > M - 1) gm = M - 1;
            cp16((uint32_t)__cvta_generic_to_shared(&As[buf][r][c]),
                 A + (size_t)gm * lda + k0 + c);
        }
        #pragma unroll
        for (int i = 0; i < B_ITERS; i++) {
            int f = tid + i * 256;
            int r = f / BROW, c = (f % BROW) * 4;
            cp16((uint32_t)__cvta_generic_to_shared(&Bs[buf][r][c]),
                 B + (size_t)(k0 + r) * N + n0 + c);
        }
        asm volatile("cp.async.commit_group;" ::: "memory");
    };

    prefetch(0, 0);
    int buf = 0;
    for (int k0 = 0; k0 < K; k0 += BK) {
        const bool has_next = (k0 + BK) < K;
        if (has_next) {
            prefetch(buf ^ 1, k0 + BK);
            asm volatile("cp.async.wait_group 1;" ::: "memory");
        } else {
            asm volatile("cp.async.wait_group 0;" ::: "memory");
        }
        __syncthreads();

        #pragma unroll
        for (int kc = 0; kc < BK; kc += 8) {
            const int mb = wm * 32 + (lane >> 2);
            const int kk = kc + (lane & 3);
            uint32_t afr[2][4];
            #pragma unroll
            for (int mt = 0; mt < 2; mt++) {
                afr[mt][0] = __float_as_uint(As[buf][mb + mt * 16    ][kk]);
                afr[mt][1] = __float_as_uint(As[buf][mb + mt * 16 + 8][kk]);
                afr[mt][2] = __float_as_uint(As[buf][mb + mt * 16    ][kk + 4]);
                afr[mt][3] = __float_as_uint(As[buf][mb + mt * 16 + 8][kk + 4]);
            }
            uint32_t bfr[NT][2];
            #pragma unroll
            for (int nt = 0; nt < NT; nt++) {
                const int kr = kc + (lane & 3);
                const int nc = wn * (BN / WN) + nt * 8 + (lane >> 2);
                bfr[nt][0] = __float_as_uint(Bs[buf][kr    ][nc]);
                bfr[nt][1] = __float_as_uint(Bs[buf][kr + 4][nc]);
            }
            #pragma unroll
            for (int mt = 0; mt < 2; mt++)
                #pragma unroll
                for (int nt = 0; nt < NT; nt++)
                    mma8(acc[mt][nt], afr[mt], bfr[nt]);
        }
        __syncthreads();
        buf ^= 1;
    }

    #pragma unroll
    for (int mt = 0; mt < 2; mt++) {
        int gm = m0 + wm * 32 + mt * 16 + (lane >> 2);
        #pragma unroll
        for (int nt = 0; nt < NT; nt++) {
            int gn = n0 + wn * (BN / WN) + nt * 8 + 2 * (lane & 3);
            float b0 = 0.f, b1 = 0.f;
            if (use_bias) { b0 = bias[gn]; b1 = bias[gn + 1]; }
            float v0 = acc[mt][nt][0] + b0, v1 = acc[mt][nt][1] + b1;
            float v2 = acc[mt][nt][2] + b0, v3 = acc[mt][nt][3] + b1;
            if (RELU) {
                v0 = fmaxf(v0, 0.f); v1 = fmaxf(v1, 0.f);
                v2 = fmaxf(v2, 0.f); v3 = fmaxf(v3, 0.f);
            }
            if (gm < M)
                *reinterpret_cast<float2*>(C + (size_t)gm * N + gn) = make_float2(v0, v1);
            if (gm + 8 < M)
                *reinterpret_cast<float2*>(C + (size_t)(gm + 8) * N + gn) = make_float2(v2, v3);
        }
    }
}

// Plain GEMM (used for ff1): C = A@B + bias (+relu)
template<int BM, int BN, int RELU>
__global__ __launch_bounds__(256) void gemm_tf32_kernel(
    const float* __restrict__ A, const float* __restrict__ B,
    const float* __restrict__ bias, float* __restrict__ C,
    int M, int N, int K)
{
    __shared__ float As[2][BM][20];
    __shared__ float Bs[2][16][BN + 4];
    gemm_body<BM, BN, RELU>(A, B, bias, C, M, N, K, K,
                            blockIdx.y * BM, blockIdx.x * BN, 1, As, Bs);
}

// Split-K=2 GEMM in ONE launch: grid(z=2). kz=0 -> C0 (+bias), kz=1 -> C1 (no bias).
template<int BM, int BN>
__global__ __launch_bounds__(256) void gemm_sk2_kernel(
    const float* __restrict__ A, const float* __restrict__ B,
    const float* __restrict__ bias, float* __restrict__ C0, float* __restrict__ C1,
    int M, int N, int Kfull)
{
    __shared__ float As[2][BM][20];
    __shared__ float Bs[2][16][BN + 4];
    const int kz = blockIdx.z;
    const int Kh = Kfull >> 1;
    gemm_body<BM, BN, 0>(A + (size_t)kz * Kh, B + (size_t)kz * Kh * N,
                         bias, kz ? C1 : C0, M, N, Kh, Kfull,
                         blockIdx.y * BM, blockIdx.x * BN, kz == 0, As, Bs);
}

// Fused val/off/attn: 5 N-tiles (val:2, off:2, attn:1) x 121 M-blocks = 605 blocks.
struct MG3 {
    const float* A[3];
    const float* B[3];
    const float* bias[3];
    float* C[3];
    int N[3];
};

__global__ __launch_bounds__(256) void gemm3_kernel(MG3 mg, int M, int K)
{
    constexpr int BM = 64, BN = 128;
    __shared__ float As[2][BM][20];
    __shared__ float Bs[2][16][BN + 4];
    const int bx  = blockIdx.x;                       // 0..4
    const int gid = (bx < 2) ? 0 : (bx < 4) ? 1 : 2;
    const int nb  = (bx == 1 || bx == 3) ? 1 : 0;
    gemm_body<BM, BN, 0>(mg.A[gid], mg.B[gid], mg.bias[gid], mg.C[gid],
                         M, mg.N[gid], K, K,
                         blockIdx.y * BM, nb * BN, 1, As, Bs);
}

// ---------------- MSDA sampling: one warp per (s, head) -------------------
__global__ __launch_bounds__(256) void msda_kernel(
    const float* __restrict__ val, const float* __restrict__ off,
    const float* __restrict__ attn, const float* __restrict__ vr,
    float* __restrict__ out)
{
    const unsigned FULL = 0xffffffffu;
    int w = blockIdx.x * 8 + (threadIdx.x >> 5);
    int lane = threadIdx.x & 31;
    if (w >= S_TOT * 8) return;
    int s = w >> 3;
    int m = w & 7;

    float logit = -INFINITY;
    if (lane < 16) logit = attn[(size_t)s * 128 + m * 16 + lane];
    float mx = logit;
    #pragma unroll
    for (int o = 16; o > 0; o >>= 1) mx = fmaxf(mx, __shfl_xor_sync(FULL, mx, o));
    float e = (lane < 16) ? expf(logit - mx) : 0.f;
    float sum = e;
    #pragma unroll
    for (int o = 16; o > 0; o >>= 1) sum += __shfl_xor_sync(FULL, sum, o);
    float wn = e / sum;

    int lvlS = (s >= 7581) ? 3 : (s >= 7220) ? 2 : (s >= 5776) ? 1 : 0;
    int idx = s - c_ST[lvlS];
    int Ws = c_W[lvlS], Hs = c_H[lvlS];
    int row = idx / Ws, col = idx - row * Ws;
    float bx = (col + 0.5f) / (vr[lvlS * 2 + 0] * (float)Ws);
    float by = (row + 0.5f) / (vr[lvlS * 2 + 1] * (float)Hs);

    float offv = off[(size_t)s * 256 + m * 32 + lane];

    float acc = 0.f;
    #pragma unroll
    for (int lvl = 0; lvl < 4; lvl++) {
        int H = c_H[lvl], W = c_W[lvl], st = c_ST[lvl];
        float refx = bx * vr[lvl * 2 + 0];
        float refy = by * vr[lvl * 2 + 1];
        #pragma unroll
        for (int p = 0; p < 4; p++) {
            float ox = __shfl_sync(FULL, offv, lvl * 8 + p * 2 + 0);
            float oy = __shfl_sync(FULL, offv, lvl * 8 + p * 2 + 1);
            float aw = __shfl_sync(FULL, wn, lvl * 4 + p);
            float lx = refx + ox / (float)W;
            float ly = refy + oy / (float)H;
            float x = lx * (float)W - 0.5f;
            float y = ly * (float)H - 0.5f;
            float x0f = floorf(x), y0f = floorf(y);
            int x0 = (int)x0f, y0 = (int)y0f;
            float dx = x - x0f, dy = y - y0f;

            float samp = 0.f;
            const float* vb = val + (size_t)st * 256 + m * 32 + lane;
            if (x0 >= 0 && x0 < W && y0 >= 0 && y0 < H)
                samp += (1.f - dy) * (1.f - dx) * vb[(size_t)(y0 * W + x0) * 256];
            if (x0 + 1 >= 0 && x0 + 1 < W && y0 >= 0 && y0 < H)
                samp += (1.f - dy) * dx * vb[(size_t)(y0 * W + x0 + 1) * 256];
            if (x0 >= 0 && x0 < W && y0 + 1 >= 0 && y0 + 1 < H)
                samp += dy * (1.f - dx) * vb[(size_t)((y0 + 1) * W + x0) * 256];
            if (x0 + 1 >= 0 && x0 + 1 < W && y0 + 1 >= 0 && y0 + 1 < H)
                samp += dy * dx * vb[(size_t)((y0 + 1) * W + x0 + 1) * 256];

            acc += aw * samp;
        }
    }
    out[(size_t)s * 256 + m * 32 + lane] = acc;
}

// ---------------- residual + split-K partials + LayerNorm (in place) ------
__device__ __forceinline__ float block_sum(float v) {
    __shared__ float sh[8];
    int lane = threadIdx.x & 31, wid = threadIdx.x >> 5;
    #pragma unroll
    for (int o = 16; o > 0; o >>= 1) v += __shfl_xor_sync(0xffffffffu, v, o);
    if (lane == 0) sh[wid] = v;
    __syncthreads();
    if (wid == 0) {
        float t = (lane < 8) ? sh[lane] : 0.f;
        #pragma unroll
        for (int o = 4; o > 0; o >>= 1) t += __shfl_xor_sync(0xffffffffu, t, o);
        if (lane == 0) sh[0] = t;
    }
    __syncthreads();
    float r = sh[0];
    __syncthreads();
    return r;
}

__global__ __launch_bounds__(256) void add3_ln_kernel(
    float* __restrict__ x, const float* __restrict__ p0, const float* __restrict__ p1,
    const float* __restrict__ g, const float* __restrict__ b)
{
    int s = blockIdx.x;
    int t = threadIdx.x;
    size_t i = (size_t)s * 256 + t;
    float v = x[i] + (p0[i] + p1[i]);
    float mean = block_sum(v) * (1.f / 256.f);
    float d = v - mean;
    float var = block_sum(d * d) * (1.f / 256.f);
    float inv = rsqrtf(var + 1e-5f);
    x[i] = d * inv * g[t] + b[t];
}

// ---------------- launch --------------------------------------------------
extern "C" void kernel_launch(void* const* d_in, const int* in_sizes, int n_in,
                              void* d_out, int out_size) {
    const float* src    = (const float*)d_in[0];
    const float* pos    = (const float*)d_in[1];
    const float* vr     = (const float*)d_in[2];
    const float* W_off  = (const float*)d_in[6];
    const float* b_off  = (const float*)d_in[7];
    const float* W_attn = (const float*)d_in[8];
    const float* b_attn = (const float*)d_in[9];
    const float* W_val  = (const float*)d_in[10];
    const float* b_val  = (const float*)d_in[11];
    const float* W_out  = (const float*)d_in[12];
    const float* b_out  = (const float*)d_in[13];
    const float* ln1_g  = (const float*)d_in[14];
    const float* ln1_b  = (const float*)d_in[15];
    const float* W_ff1  = (const float*)d_in[16];
    const float* b_ff1  = (const float*)d_in[17];
    const float* W_ff2  = (const float*)d_in[18];
    const float* b_ff2  = (const float*)d_in[19];
    const float* ln2_g  = (const float*)d_in[20];
    const float* ln2_b  = (const float*)d_in[21];

    float* x = (float*)d_out;   // running activation, ends as the output

    float *q, *val, *off, *attn, *samp, *tmp, *tmp2, *ffh;
    cudaGetSymbolAddress((void**)&q,    g_q);
    cudaGetSymbolAddress((void**)&val,  g_val);
    cudaGetSymbolAddress((void**)&off,  g_off);
    cudaGetSymbolAddress((void**)&attn, g_attn);
    cudaGetSymbolAddress((void**)&samp, g_samp);
    cudaGetSymbolAddress((void**)&tmp,  g_tmp);
    cudaGetSymbolAddress((void**)&tmp2, g_tmp2);
    cudaGetSymbolAddress((void**)&ffh,  g_ffh);

    const int S = S_TOT;
    const int MB64  = 121;                    // ceil(7681/64)
    const int MB128 = 61;                     // ceil(7681/128)
    const dim3 g3(5, MB64);                   // fused val/off/attn: 605 blocks
    const dim3 gsk(2, MB64, 2);               // split-K=2, N=256: 484 blocks
    const dim3 g1024(8, MB128);               // ff1: 488 blocks

    copy_kernel<<<S, 256>>>(x, src);

    for (int l = 0; l < 3; l++) {
        add_kernel<<<S, 256>>>(q, x, pos);

        MG3 mg;
        mg.A[0] = x;    mg.B[0] = W_val  + (size_t)l * 65536; mg.bias[0] = b_val  + l * 256; mg.C[0] = val;  mg.N[0] = 256;
        mg.A[1] = q;    mg.B[1] = W_off  + (size_t)l * 65536; mg.bias[1] = b_off  + l * 256; mg.C[1] = off;  mg.N[1] = 256;
        mg.A[2] = q;    mg.B[2] = W_attn + (size_t)l * 32768; mg.bias[2] = b_attn + l * 128; mg.C[2] = attn; mg.N[2] = 128;
        gemm3_kernel<<<g3, 256>>>(mg, S, 256);

        msda_kernel<<<S, 256>>>(val, off, attn, vr, samp);

        gemm_sk2_kernel<64, 128><<<gsk, 256>>>(samp, W_out + (size_t)l * 65536,
                                               b_out + l * 256, tmp, tmp2, S, 256, 256);
        add3_ln_kernel<<<S, 256>>>(x, tmp, tmp2, ln1_g + l * 256, ln1_b + l * 256);

        gemm_tf32_kernel<128, 128, 1><<<g1024, 256>>>(x, W_ff1 + (size_t)l * 262144,
                                                      b_ff1 + l * 1024, ffh, S, 1024, 256);
        gemm_sk2_kernel<64, 128><<<gsk, 256>>>(ffh, W_ff2 + (size_t)l * 262144,
                                               b_ff2 + l * 256, tmp, tmp2, S, 256, 1024);
        add3_ln_kernel<<<S, 256>>>(x, tmp, tmp2, ln2_g + l * 256, ln2_b + l * 256);
    }
}